// round 4
// baseline (speedup 1.0000x reference)
#include <cuda_runtime.h>
#include <math.h>

// TTTLinearAdaptation: B=4, H=16, S=8192, D=64, CHUNK=16 -> 64 sequences x 512 chunks.
// One CTA per (b,h), 512 threads. W[64x64] state in SMEM for the whole scan.
// lane = (dh, c_in, eg8): dh splits the K-dim of the matmuls (reduced by shfl.xor 16),
// warp = (cg8, eh): 2 chunk-rows x one 32-col half.

namespace {
constexpr int Dd      = 64;
constexpr int Cc      = 16;
constexpr int NCH     = 512;   // 8192 / 16
constexpr int THREADS = 512;
constexpr int NUM_BH  = 64;
}

__device__ __forceinline__ void cp_async16(void* sm, const void* gm) {
    unsigned a = (unsigned)__cvta_generic_to_shared(sm);
    asm volatile("cp.async.cg.shared.global [%0], [%1], 16;" :: "r"(a), "l"(gm));
}

__global__ void __launch_bounds__(THREADS, 1)
ttt_linear_kernel(const float* __restrict__ xq, const float* __restrict__ xk,
                  const float* __restrict__ xv, const float* __restrict__ W0,
                  const float* __restrict__ b0, const float* __restrict__ gamma_,
                  const float* __restrict__ beta_, const float* __restrict__ theta_,
                  const float* __restrict__ theta_bias, const float* __restrict__ alpha,
                  float* __restrict__ out)
{
    __shared__ float  W_s[Dd * Dd];                 // 16 KB persistent state
    __shared__ float4 buf[2][3 * Cc * Dd / 4];      // 24 KB double-buffered q,k,v
    __shared__ float  egx_s[Cc * Dd];               // eta*grad_x, 4 KB
    __shared__ float  b_s[Dd];
    __shared__ float2 sred[Cc][2], gred[Cc][2], tred[Cc][2];

    const int tid  = threadIdx.x;
    const int lane = tid & 31;
    const int w    = tid >> 5;
    const int eh   = w & 1;
    const int cg8  = w >> 1;
    const int dh   = lane >> 4;
    const int c_in = (lane >> 3) & 1;
    const int eg8  = lane & 7;
    const int c    = cg8 * 2 + c_in;
    const int e0   = eh * 32 + eg8 * 4;
    const int dbase = dh * 32;

    const int bh = blockIdx.x;
    const int h  = bh & 15;
    const size_t base = (size_t)bh * (size_t)(NCH * Cc * Dd);

    // ---- init persistent state ----
    #pragma unroll
    for (int j = 0; j < 8; ++j) W_s[tid + j * THREADS] = W0[h * Dd * Dd + tid + j * THREADS];
    if (tid < Dd) b_s[tid] = b0[h * Dd + tid];

    // per-thread constants from global
    const float4 gm4 = *(const float4*)(gamma_ + h * Dd + e0);
    const float4 bt4 = *(const float4*)(beta_  + h * Dd + e0);
    const float4 th4 = *(const float4*)(theta_ + h * Dd + dbase + eg8 * 4);
    const float  tb  = __ldg(theta_bias + h);
    const float  tok_c = fmaxf(1.0f / (float)(c + 1) + __ldg(alpha + c), 0.0f);

    // ---- prefetch chunk 0 ----  (768 float4: [q|k|v] x 256 each)
    {
        const float* srcs[3] = { xq + base, xk + base, xv + base };
        int idx = tid;
        cp_async16(&buf[0][idx], (const float4*)srcs[idx >> 8] + (idx & 255));
        if (tid < 256) {
            idx = tid + 512;
            cp_async16(&buf[0][idx], (const float4*)srcs[idx >> 8] + (idx & 255));
        }
        asm volatile("cp.async.commit_group;");
    }

    for (int i = 0; i < NCH; ++i) {
        // ---- prefetch next chunk into other buffer ----
        {
            const int    ni = (i + 1 < NCH) ? (i + 1) : (NCH - 1);
            const int    nb = (i + 1) & 1;
            const size_t no = base + (size_t)ni * (Cc * Dd);
            const float* srcs[3] = { xq + no, xk + no, xv + no };
            int idx = tid;
            cp_async16(&buf[nb][idx], (const float4*)srcs[idx >> 8] + (idx & 255));
            if (tid < 256) {
                idx = tid + 512;
                cp_async16(&buf[nb][idx], (const float4*)srcs[idx >> 8] + (idx & 255));
            }
            asm volatile("cp.async.commit_group;");
        }
        asm volatile("cp.async.wait_group 1;");
        __syncthreads();                                    // A: buf[i&1] visible

        const float* qs = (const float*)&buf[i & 1][0];
        const float* ks = qs + Cc * Dd;
        const float* vs = qs + 2 * Cc * Dd;

        // ============ Z = k @ W + b (this thread: row c, cols e0..e0+3, K-half dbase) ====
        float a0 = 0.f, a1 = 0.f, a2 = 0.f, a3 = 0.f;
        #pragma unroll
        for (int j = 0; j < 8; ++j) {
            const float4 kv = *(const float4*)(ks + c * Dd + dbase + j * 4);
            #pragma unroll
            for (int jj = 0; jj < 4; ++jj) {
                const float  kj = (&kv.x)[jj];
                const float4 wv = *(const float4*)(W_s + (dbase + j * 4 + jj) * Dd + e0);
                a0 = fmaf(kj, wv.x, a0); a1 = fmaf(kj, wv.y, a1);
                a2 = fmaf(kj, wv.z, a2); a3 = fmaf(kj, wv.w, a3);
            }
        }
        // combine the two K-halves (lanes differing in bit 4)
        a0 += __shfl_xor_sync(0xffffffffu, a0, 16);
        a1 += __shfl_xor_sync(0xffffffffu, a1, 16);
        a2 += __shfl_xor_sync(0xffffffffu, a2, 16);
        a3 += __shfl_xor_sync(0xffffffffu, a3, 16);

        const float4 bv = *(const float4*)(b_s + e0);
        const float z0 = a0 + bv.x, z1 = a1 + bv.y, z2 = a2 + bv.z, z3 = a3 + bv.w;

        // k . theta : d-slice dbase+eg8*4, reduced over eg8 (xor 1,2,4) and dh (xor 16)
        const float4 k4d = *(const float4*)(ks + c * Dd + dbase + eg8 * 4);
        float kth = k4d.x * th4.x + k4d.y * th4.y + k4d.z * th4.z + k4d.w * th4.w;

        float s1 = z0 + z1 + z2 + z3;
        float s2 = z0 * z0 + z1 * z1 + z2 * z2 + z3 * z3;
        #pragma unroll
        for (int m = 1; m <= 4; m <<= 1) {
            s1  += __shfl_xor_sync(0xffffffffu, s1,  m);
            s2  += __shfl_xor_sync(0xffffffffu, s2,  m);
            kth += __shfl_xor_sync(0xffffffffu, kth, m);
        }
        kth += __shfl_xor_sync(0xffffffffu, kth, 16);

        if (lane == 0 || lane == 8) sred[c][eh] = make_float2(s1, s2);
        __syncthreads();                                    // B
        {
            const float2 sp = sred[c][eh ^ 1];
            s1 += sp.x; s2 += sp.y;
        }
        const float mu   = s1 * (1.0f / 64.0f);
        const float var  = s2 * (1.0f / 64.0f) - mu * mu;
        const float rstd = rsqrtf(fmaxf(var, 0.0f) + 1e-6f);
        const float eta  = tok_c * (1.0f / 64.0f) / (1.0f + __expf(-(kth + tb)));

        const float xh0 = (z0 - mu) * rstd, xh1 = (z1 - mu) * rstd;
        const float xh2 = (z2 - mu) * rstd, xh3 = (z3 - mu) * rstd;
        const float4 v4  = *(const float4*)(vs + c * Dd + e0);
        const float4 k4e = *(const float4*)(ks + c * Dd + e0);
        const float g0 = (fmaf(gm4.x, xh0, bt4.x) - (v4.x - k4e.x)) * gm4.x;
        const float g1 = (fmaf(gm4.y, xh1, bt4.y) - (v4.y - k4e.y)) * gm4.y;
        const float g2 = (fmaf(gm4.z, xh2, bt4.z) - (v4.z - k4e.z)) * gm4.z;
        const float g3 = (fmaf(gm4.w, xh3, bt4.w) - (v4.w - k4e.w)) * gm4.w;

        float sg  = g0 + g1 + g2 + g3;
        float sgx = g0 * xh0 + g1 * xh1 + g2 * xh2 + g3 * xh3;
        #pragma unroll
        for (int m = 1; m <= 4; m <<= 1) {
            sg  += __shfl_xor_sync(0xffffffffu, sg,  m);
            sgx += __shfl_xor_sync(0xffffffffu, sgx, m);
        }
        if (lane == 0 || lane == 8) gred[c][eh] = make_float2(sg, sgx);
        __syncthreads();                                    // C
        {
            const float2 gp = gred[c][eh ^ 1];
            sg += gp.x; sgx += gp.y;
        }
        const float cf = rstd * (1.0f / 64.0f) * eta;       // eta folded: egx = eta*gx
        float4 egx;
        egx.x = (64.0f * g0 - sg - xh0 * sgx) * cf;
        egx.y = (64.0f * g1 - sg - xh1 * sgx) * cf;
        egx.z = (64.0f * g2 - sg - xh2 * sgx) * cf;
        egx.w = (64.0f * g3 - sg - xh3 * sgx) * cf;
        if (dh == 0) *(float4*)(egx_s + c * Dd + e0) = egx;
        __syncthreads();                                    // D: egx ready

        // ============ W -= k^T @ egx ;  b -= sum(egx) ============
        {
            const int dd = tid >> 3;         // W row 0..63
            const int et = tid & 7;          // column quads et*4 and 32+et*4 (bank-spread)
            const int ea = et * 4, eb = 32 + et * 4;
            float A0=0.f,A1=0.f,A2=0.f,A3=0.f,B0=0.f,B1=0.f,B2=0.f,B3=0.f;
            #pragma unroll
            for (int cc = 0; cc < Cc; ++cc) {
                const float  kv = ks[cc * Dd + dd];
                const float4 ga = *(const float4*)(egx_s + cc * Dd + ea);
                const float4 gb = *(const float4*)(egx_s + cc * Dd + eb);
                A0 = fmaf(kv, ga.x, A0); A1 = fmaf(kv, ga.y, A1);
                A2 = fmaf(kv, ga.z, A2); A3 = fmaf(kv, ga.w, A3);
                B0 = fmaf(kv, gb.x, B0); B1 = fmaf(kv, gb.y, B1);
                B2 = fmaf(kv, gb.z, B2); B3 = fmaf(kv, gb.w, B3);
            }
            float4* wa = (float4*)(W_s + dd * Dd + ea);
            float4* wb = (float4*)(W_s + dd * Dd + eb);
            float4 va = *wa, vb = *wb;
            va.x -= A0; va.y -= A1; va.z -= A2; va.w -= A3;
            vb.x -= B0; vb.y -= B1; vb.z -= B2; vb.w -= B3;
            *wa = va; *wb = vb;
        }
        if (tid < Dd) {
            float db = 0.0f;
            #pragma unroll
            for (int cc = 0; cc < Cc; ++cc) db += egx_s[cc * Dd + tid];
            b_s[tid] -= db;
        }
        __syncthreads();                                    // E: W', b' ready

        // ============ Zq = q @ W' + b', out = q + LN(Zq) ============
        float p0 = 0.f, p1 = 0.f, p2 = 0.f, p3 = 0.f;
        #pragma unroll
        for (int j = 0; j < 8; ++j) {
            const float4 qv = *(const float4*)(qs + c * Dd + dbase + j * 4);
            #pragma unroll
            for (int jj = 0; jj < 4; ++jj) {
                const float  qj = (&qv.x)[jj];
                const float4 wv = *(const float4*)(W_s + (dbase + j * 4 + jj) * Dd + e0);
                p0 = fmaf(qj, wv.x, p0); p1 = fmaf(qj, wv.y, p1);
                p2 = fmaf(qj, wv.z, p2); p3 = fmaf(qj, wv.w, p3);
            }
        }
        p0 += __shfl_xor_sync(0xffffffffu, p0, 16);
        p1 += __shfl_xor_sync(0xffffffffu, p1, 16);
        p2 += __shfl_xor_sync(0xffffffffu, p2, 16);
        p3 += __shfl_xor_sync(0xffffffffu, p3, 16);

        const float4 bn = *(const float4*)(b_s + e0);
        const float u0 = p0 + bn.x, u1 = p1 + bn.y, u2 = p2 + bn.z, u3 = p3 + bn.w;

        float t1 = u0 + u1 + u2 + u3;
        float t2 = u0 * u0 + u1 * u1 + u2 * u2 + u3 * u3;
        #pragma unroll
        for (int m = 1; m <= 4; m <<= 1) {
            t1 += __shfl_xor_sync(0xffffffffu, t1, m);
            t2 += __shfl_xor_sync(0xffffffffu, t2, m);
        }
        // hoist ALL buf reads before the barrier (next iter's prefetch reuses this buffer)
        const float4 q4e = *(const float4*)(qs + c * Dd + e0);
        if (lane == 0 || lane == 8) tred[c][eh] = make_float2(t1, t2);
        __syncthreads();                                    // F
        {
            const float2 tp = tred[c][eh ^ 1];
            t1 += tp.x; t2 += tp.y;
        }
        const float mu2   = t1 * (1.0f / 64.0f);
        const float var2  = t2 * (1.0f / 64.0f) - mu2 * mu2;
        const float rstd2 = rsqrtf(fmaxf(var2, 0.0f) + 1e-6f);

        if (dh == 0) {
            float4 o;
            o.x = q4e.x + fmaf(gm4.x, (u0 - mu2) * rstd2, bt4.x);
            o.y = q4e.y + fmaf(gm4.y, (u1 - mu2) * rstd2, bt4.y);
            o.z = q4e.z + fmaf(gm4.z, (u2 - mu2) * rstd2, bt4.z);
            o.w = q4e.w + fmaf(gm4.w, (u3 - mu2) * rstd2, bt4.w);
            *(float4*)(out + base + (size_t)i * (Cc * Dd) + c * Dd + e0) = o;
        }
    }
    asm volatile("cp.async.wait_group 0;");
}

extern "C" void kernel_launch(void* const* d_in, const int* in_sizes, int n_in,
                              void* d_out, int out_size) {
    (void)in_sizes; (void)n_in; (void)out_size;
    const float* xq         = (const float*)d_in[0];
    const float* xk         = (const float*)d_in[1];
    const float* xv         = (const float*)d_in[2];
    const float* W0         = (const float*)d_in[3];
    const float* b0         = (const float*)d_in[4];
    const float* gamma_     = (const float*)d_in[5];
    const float* beta_      = (const float*)d_in[6];
    const float* theta_     = (const float*)d_in[7];
    const float* theta_bias = (const float*)d_in[8];
    const float* alpha      = (const float*)d_in[9];
    float* out = (float*)d_out;

    ttt_linear_kernel<<<NUM_BH, THREADS>>>(xq, xk, xv, W0, b0, gamma_, beta_,
                                           theta_, theta_bias, alpha, out);
}

// round 5
// speedup vs baseline: 1.2089x; 1.2089x over previous
#include <cuda_runtime.h>
#include <math.h>

// TTTLinearAdaptation: B=4,H=16,S=8192,D=64,C=16 -> 64 seqs x 512 chunks.
// One CTA/(b,h), 512 threads = 16 warps.
//   warps 0-7  ("q-side"): row r=tid>>4 (0..15) of q; produce output for chunk t-1.
//   warps 8-15 ("k-side"): row kr=r-16 of k; produce gradient for chunk t.
// Combined matmul per chunk: [q(t);k(t+1)] (32x64) @ W(t+1) (64x64).
// W-update tile (8 floats/thread) lives in registers, mirrored to SMEM.

namespace {
constexpr int Dd      = 64;
constexpr int Cc      = 16;
constexpr int NCH     = 512;
constexpr int THREADS = 512;
constexpr int NUM_BH  = 64;
}

__device__ __forceinline__ void cp_async16(void* sm, const void* gm) {
    unsigned a = (unsigned)__cvta_generic_to_shared(sm);
    asm volatile("cp.async.cg.shared.global [%0], [%1], 16;" :: "r"(a), "l"(gm));
}

// Prefetch one chunk (q,k,v = 3*256 float4) into dst; one commit_group.
__device__ __forceinline__ void prefetch_chunk(float4* dst,
                                               const float* xq, const float* xk,
                                               const float* xv, size_t off, int tid) {
    if (tid < 256) {
        cp_async16(dst + tid,       (const float4*)(xq + off) + tid);
        cp_async16(dst + 512 + tid, (const float4*)(xv + off) + tid);
    } else {
        cp_async16(dst + tid,       (const float4*)(xk + off) + (tid - 256));
    }
    asm volatile("cp.async.commit_group;");
}

__global__ void __launch_bounds__(THREADS, 1)
ttt_linear_kernel(const float* __restrict__ xq, const float* __restrict__ xk,
                  const float* __restrict__ xv, const float* __restrict__ W0,
                  const float* __restrict__ b0, const float* __restrict__ gamma_,
                  const float* __restrict__ beta_, const float* __restrict__ theta_,
                  const float* __restrict__ theta_bias, const float* __restrict__ alpha,
                  float* __restrict__ out)
{
    __shared__ float  W_s[Dd * Dd];            // 16 KB, mirror of register-held state
    __shared__ float4 buf[2][768];             // 24 KB: q[0:256) k[256:512) v[512:768)
    __shared__ float  egx_s[Cc * Dd];          // eta*grad_x
    __shared__ float  b_s[Dd];

    const int tid  = threadIdx.x;
    const int r    = tid >> 4;       // 0..31
    const int eg   = tid & 15;
    const int e0   = eg * 4;
    const int kr   = r & 15;         // row within chunk
    const bool qside = (r < 16);     // warp-uniform

    const int bh = blockIdx.x;
    const int h  = bh & 15;
    const size_t base = (size_t)bh * (size_t)(NCH * Cc * Dd);

    // W-update ownership: row wd = tid>>3, col quads ea / eb (bank-spread)
    const int wd  = tid >> 3;
    const int wet = tid & 7;
    const int ea  = wet * 4, eb = 32 + wet * 4;

    float4 wra, wrb;                 // register-resident W state (8 floats)
    {
        const float* wsrc = W0 + h * Dd * Dd + wd * Dd;
        wra = *(const float4*)(wsrc + ea);
        wrb = *(const float4*)(wsrc + eb);
        *(float4*)(W_s + wd * Dd + ea) = wra;
        *(float4*)(W_s + wd * Dd + eb) = wrb;
    }
    if (tid < Dd) b_s[tid] = b0[h * Dd + tid];

    const float4 gm4 = *(const float4*)(gamma_ + h * Dd + e0);
    const float4 bt4 = *(const float4*)(beta_  + h * Dd + e0);
    const float4 th4 = *(const float4*)(theta_ + h * Dd + e0);
    const float  tb  = __ldg(theta_bias + h);
    const float  tok_c = fmaxf(1.0f / (float)(kr + 1) + __ldg(alpha + kr), 0.0f);

    // ---- prefetch chunks 0,1 (two groups) ----
    prefetch_chunk(buf[0], xq, xk, xv, base, tid);
    prefetch_chunk(buf[1], xq, xk, xv, base + (size_t)(Cc * Dd), tid);
    asm volatile("cp.async.wait_group 1;");
    __syncthreads();

    float z0 = 0.f, z1 = 0.f, z2 = 0.f, z3 = 0.f;
    float4 q4e = make_float4(0.f, 0.f, 0.f, 0.f);

    // ---- prologue: k-side computes Zk(0) = k(0) @ W0 + b0 ----
    if (!qside) {
        const float* src = (const float*)buf[0] + 1024 + kr * Dd;
        #pragma unroll
        for (int j = 0; j < 16; ++j) {
            const float4 s4 = *(const float4*)(src + j * 4);
            const float4 w0 = *(const float4*)(W_s + (j * 4 + 0) * Dd + e0);
            const float4 w1 = *(const float4*)(W_s + (j * 4 + 1) * Dd + e0);
            const float4 w2 = *(const float4*)(W_s + (j * 4 + 2) * Dd + e0);
            const float4 w3 = *(const float4*)(W_s + (j * 4 + 3) * Dd + e0);
            z0 = fmaf(s4.x, w0.x, z0); z1 = fmaf(s4.x, w0.y, z1);
            z2 = fmaf(s4.x, w0.z, z2); z3 = fmaf(s4.x, w0.w, z3);
            z0 = fmaf(s4.y, w1.x, z0); z1 = fmaf(s4.y, w1.y, z1);
            z2 = fmaf(s4.y, w1.z, z2); z3 = fmaf(s4.y, w1.w, z3);
            z0 = fmaf(s4.z, w2.x, z0); z1 = fmaf(s4.z, w2.y, z1);
            z2 = fmaf(s4.z, w2.z, z2); z3 = fmaf(s4.z, w2.w, z3);
            z0 = fmaf(s4.w, w3.x, z0); z1 = fmaf(s4.w, w3.y, z1);
            z2 = fmaf(s4.w, w3.z, z2); z3 = fmaf(s4.w, w3.w, z3);
        }
        const float4 bn = *(const float4*)(b_s + e0);
        z0 += bn.x; z1 += bn.y; z2 += bn.z; z3 += bn.w;
    }

    for (int t = 0; t < NCH; ++t) {
        const float* curq = (const float*)buf[t & 1];
        const float* curk = curq + 1024;
        const float* curv = curq + 2048;

        // ================== step 1 (concurrent per warp-group) ==================
        if (!qside) {
            // gradient for chunk t from Zk(t) in regs
            const float4 k4e = *(const float4*)(curk + kr * Dd + e0);
            const float4 v4  = *(const float4*)(curv + kr * Dd + e0);
            float kth = k4e.x * th4.x + k4e.y * th4.y + k4e.z * th4.z + k4e.w * th4.w;
            float s1 = z0 + z1 + z2 + z3;
            float s2 = z0 * z0 + z1 * z1 + z2 * z2 + z3 * z3;
            #pragma unroll
            for (int m = 1; m <= 8; m <<= 1) {
                s1  += __shfl_xor_sync(0xffffffffu, s1,  m);
                s2  += __shfl_xor_sync(0xffffffffu, s2,  m);
                kth += __shfl_xor_sync(0xffffffffu, kth, m);
            }
            const float mu   = s1 * (1.0f / 64.0f);
            const float var  = s2 * (1.0f / 64.0f) - mu * mu;
            const float rstd = rsqrtf(fmaxf(var, 0.0f) + 1e-6f);
            const float eta  = tok_c * (1.0f / 64.0f) / (1.0f + __expf(-(kth + tb)));

            const float xh0 = (z0 - mu) * rstd, xh1 = (z1 - mu) * rstd;
            const float xh2 = (z2 - mu) * rstd, xh3 = (z3 - mu) * rstd;
            const float g0 = (fmaf(gm4.x, xh0, bt4.x) - (v4.x - k4e.x)) * gm4.x;
            const float g1 = (fmaf(gm4.y, xh1, bt4.y) - (v4.y - k4e.y)) * gm4.y;
            const float g2 = (fmaf(gm4.z, xh2, bt4.z) - (v4.z - k4e.z)) * gm4.z;
            const float g3 = (fmaf(gm4.w, xh3, bt4.w) - (v4.w - k4e.w)) * gm4.w;

            float sg  = g0 + g1 + g2 + g3;
            float sgx = g0 * xh0 + g1 * xh1 + g2 * xh2 + g3 * xh3;
            #pragma unroll
            for (int m = 1; m <= 8; m <<= 1) {
                sg  += __shfl_xor_sync(0xffffffffu, sg,  m);
                sgx += __shfl_xor_sync(0xffffffffu, sgx, m);
            }
            const float cf = rstd * (1.0f / 64.0f) * eta;  // egx = eta * grad_x
            float4 egx;
            egx.x = (64.0f * g0 - sg - xh0 * sgx) * cf;
            egx.y = (64.0f * g1 - sg - xh1 * sgx) * cf;
            egx.z = (64.0f * g2 - sg - xh2 * sgx) * cf;
            egx.w = (64.0f * g3 - sg - xh3 * sgx) * cf;
            *(float4*)(egx_s + kr * Dd + e0) = egx;
        } else if (t > 0) {
            // output for chunk t-1 from Zq(t-1) in regs + carried q slice
            float t1 = z0 + z1 + z2 + z3;
            float t2 = z0 * z0 + z1 * z1 + z2 * z2 + z3 * z3;
            #pragma unroll
            for (int m = 1; m <= 8; m <<= 1) {
                t1 += __shfl_xor_sync(0xffffffffu, t1, m);
                t2 += __shfl_xor_sync(0xffffffffu, t2, m);
            }
            const float mu2   = t1 * (1.0f / 64.0f);
            const float var2  = t2 * (1.0f / 64.0f) - mu2 * mu2;
            const float rstd2 = rsqrtf(fmaxf(var2, 0.0f) + 1e-6f);
            float4 o;
            o.x = q4e.x + fmaf(gm4.x, (z0 - mu2) * rstd2, bt4.x);
            o.y = q4e.y + fmaf(gm4.y, (z1 - mu2) * rstd2, bt4.y);
            o.z = q4e.z + fmaf(gm4.z, (z2 - mu2) * rstd2, bt4.z);
            o.w = q4e.w + fmaf(gm4.w, (z3 - mu2) * rstd2, bt4.w);
            *(float4*)(out + base + (size_t)(t - 1) * (Cc * Dd) + kr * Dd + e0) = o;
        }
        __syncthreads();                                   // B: egx_s ready

        // ================== step 2: W -= k^T @ egx, b -= colsum(egx) ==================
        {
            float A0=0.f,A1=0.f,A2=0.f,A3=0.f,B0=0.f,B1=0.f,B2=0.f,B3=0.f;
            #pragma unroll
            for (int cc = 0; cc < Cc; ++cc) {
                const float  kv = curk[cc * Dd + wd];
                const float4 ga = *(const float4*)(egx_s + cc * Dd + ea);
                const float4 gb = *(const float4*)(egx_s + cc * Dd + eb);
                A0 = fmaf(kv, ga.x, A0); A1 = fmaf(kv, ga.y, A1);
                A2 = fmaf(kv, ga.z, A2); A3 = fmaf(kv, ga.w, A3);
                B0 = fmaf(kv, gb.x, B0); B1 = fmaf(kv, gb.y, B1);
                B2 = fmaf(kv, gb.z, B2); B3 = fmaf(kv, gb.w, B3);
            }
            wra.x -= A0; wra.y -= A1; wra.z -= A2; wra.w -= A3;
            wrb.x -= B0; wrb.y -= B1; wrb.z -= B2; wrb.w -= B3;
            *(float4*)(W_s + wd * Dd + ea) = wra;
            *(float4*)(W_s + wd * Dd + eb) = wrb;
        }
        if (tid < Dd) {
            float db = 0.0f;
            #pragma unroll
            for (int cc = 0; cc < Cc; ++cc) db += egx_s[cc * Dd + tid];
            b_s[tid] -= db;
        }
        asm volatile("cp.async.wait_group 0;");            // chunk t+1 landed
        __syncthreads();                                   // C: W', b', buf[t+1] visible

        // ================== step 3: combined matmul [q(t); k(t+1)] @ W' ==================
        {
            const float* src = qside ? (curq + kr * Dd)
                                     : ((const float*)buf[(t + 1) & 1] + 1024 + kr * Dd);
            float p0 = 0.f, p1 = 0.f, p2 = 0.f, p3 = 0.f;
            #pragma unroll
            for (int j = 0; j < 16; ++j) {
                const float4 s4 = *(const float4*)(src + j * 4);
                const float4 w0 = *(const float4*)(W_s + (j * 4 + 0) * Dd + e0);
                const float4 w1 = *(const float4*)(W_s + (j * 4 + 1) * Dd + e0);
                const float4 w2 = *(const float4*)(W_s + (j * 4 + 2) * Dd + e0);
                const float4 w3 = *(const float4*)(W_s + (j * 4 + 3) * Dd + e0);
                p0 = fmaf(s4.x, w0.x, p0); p1 = fmaf(s4.x, w0.y, p1);
                p2 = fmaf(s4.x, w0.z, p2); p3 = fmaf(s4.x, w0.w, p3);
                p0 = fmaf(s4.y, w1.x, p0); p1 = fmaf(s4.y, w1.y, p1);
                p2 = fmaf(s4.y, w1.z, p2); p3 = fmaf(s4.y, w1.w, p3);
                p0 = fmaf(s4.z, w2.x, p0); p1 = fmaf(s4.z, w2.y, p1);
                p2 = fmaf(s4.z, w2.z, p2); p3 = fmaf(s4.z, w2.w, p3);
                p0 = fmaf(s4.w, w3.x, p0); p1 = fmaf(s4.w, w3.y, p1);
                p2 = fmaf(s4.w, w3.z, p2); p3 = fmaf(s4.w, w3.w, p3);
            }
            if (qside) q4e = *(const float4*)(src + e0);   // carry residual slice
            const float4 bn = *(const float4*)(b_s + e0);
            z0 = p0 + bn.x; z1 = p1 + bn.y; z2 = p2 + bn.z; z3 = p3 + bn.w;
        }
        __syncthreads();                                   // F: buf[t&1] free

        // prefetch chunk t+2 (clamped) into buf[t&1]
        {
            const int nt = (t + 2 < NCH) ? (t + 2) : (NCH - 1);
            prefetch_chunk(buf[t & 1], xq, xk, xv,
                           base + (size_t)nt * (Cc * Dd), tid);
        }
    }

    // ---- epilogue: output chunk NCH-1 (q-side) ----
    if (qside) {
        float t1 = z0 + z1 + z2 + z3;
        float t2 = z0 * z0 + z1 * z1 + z2 * z2 + z3 * z3;
        #pragma unroll
        for (int m = 1; m <= 8; m <<= 1) {
            t1 += __shfl_xor_sync(0xffffffffu, t1, m);
            t2 += __shfl_xor_sync(0xffffffffu, t2, m);
        }
        const float mu2   = t1 * (1.0f / 64.0f);
        const float var2  = t2 * (1.0f / 64.0f) - mu2 * mu2;
        const float rstd2 = rsqrtf(fmaxf(var2, 0.0f) + 1e-6f);
        float4 o;
        o.x = q4e.x + fmaf(gm4.x, (z0 - mu2) * rstd2, bt4.x);
        o.y = q4e.y + fmaf(gm4.y, (z1 - mu2) * rstd2, bt4.y);
        o.z = q4e.z + fmaf(gm4.z, (z2 - mu2) * rstd2, bt4.z);
        o.w = q4e.w + fmaf(gm4.w, (z3 - mu2) * rstd2, bt4.w);
        *(float4*)(out + base + (size_t)(NCH - 1) * (Cc * Dd) + kr * Dd + e0) = o;
    }
    asm volatile("cp.async.wait_group 0;");
}

extern "C" void kernel_launch(void* const* d_in, const int* in_sizes, int n_in,
                              void* d_out, int out_size) {
    (void)in_sizes; (void)n_in; (void)out_size;
    const float* xq         = (const float*)d_in[0];
    const float* xk         = (const float*)d_in[1];
    const float* xv         = (const float*)d_in[2];
    const float* W0         = (const float*)d_in[3];
    const float* b0         = (const float*)d_in[4];
    const float* gamma_     = (const float*)d_in[5];
    const float* beta_      = (const float*)d_in[6];
    const float* theta_     = (const float*)d_in[7];
    const float* theta_bias = (const float*)d_in[8];
    const float* alpha      = (const float*)d_in[9];
    float* out = (float*)d_out;

    ttt_linear_kernel<<<NUM_BH, THREADS>>>(xq, xk, xv, W0, b0, gamma_, beta_,
                                           theta_, theta_bias, alpha, out);
}